// round 2
// baseline (speedup 1.0000x reference)
#include <cuda_runtime.h>

#define BN 8
#define CC 64
#define MM 256
#define NNX 256
#define MN (MM*NNX)          // 65536
#define TOTPIX (BN*MN)       // 524288

__device__ float g_avg[TOTPIX];
__device__ float g_mx [TOTPIX];
__device__ float g_sa [TOTPIX];
__device__ float g_gam[TOTPIX];
__device__ float g_bet[TOTPIX];
__device__ unsigned char g_mask[TOTPIX];
__device__ double g_all[CC*2];        // s_all, q_all per channel
__device__ double g_m  [CC*2];        // s1, q1 (masked) per channel
__device__ unsigned int g_np;
__device__ unsigned int g_flag[BN*16];  // per (batch, 16-row band) mask-present flag
__device__ float g_params[CC*4];      // mu1, a1, mu2, a2 per channel

// ---------------- K0: zero accumulators ----------------
__global__ void k0_zero() {
    int t = threadIdx.x;
    if (t < CC*2) { g_all[t] = 0.0; g_m[t] = 0.0; }
    if (t < BN*16) g_flag[t] = 0u;
    if (t == 0)   g_np = 0u;
}

// ---------------- K1: channel avg + max + per-channel total sums ----------------
__global__ void k1_avgmax(const float* __restrict__ x) {
    __shared__ float ws[8][2*CC];
    const int t    = threadIdx.x;
    const int tid  = blockIdx.x * 256 + t;
    const int base = tid * 4;
    const int b    = base >> 16;
    const int pix  = base & (MN - 1);
    const float* xb = x + ((size_t)b << 22) + pix;
    const int lane = t & 31, w = t >> 5;

    float4 s, mx;
#pragma unroll 4
    for (int c = 0; c < CC; c++) {
        float4 v = *(const float4*)(xb + ((size_t)c << 16));
        float sc = (v.x + v.y) + (v.z + v.w);
        float qc = fmaf(v.x, v.x, fmaf(v.y, v.y, fmaf(v.z, v.z, v.w * v.w)));
        if (c == 0) { s = v; mx = v; }
        else {
            s.x += v.x; s.y += v.y; s.z += v.z; s.w += v.w;
            mx.x = fmaxf(mx.x, v.x); mx.y = fmaxf(mx.y, v.y);
            mx.z = fmaxf(mx.z, v.z); mx.w = fmaxf(mx.w, v.w);
        }
#pragma unroll
        for (int o = 16; o; o >>= 1) {
            sc += __shfl_down_sync(0xffffffffu, sc, o);
            qc += __shfl_down_sync(0xffffffffu, qc, o);
        }
        if (lane == 0) { ws[w][2*c] = sc; ws[w][2*c+1] = qc; }
    }
    const float inv = 1.0f / 64.0f;
    float4 a; a.x = s.x*inv; a.y = s.y*inv; a.z = s.z*inv; a.w = s.w*inv;
    *(float4*)(g_avg + base) = a;
    *(float4*)(g_mx  + base) = mx;
    __syncthreads();
    if (t < 2*CC) {
        float v = 0.f;
#pragma unroll
        for (int i = 0; i < 8; i++) v += ws[i][t];
        atomicAdd(&g_all[t], (double)v);
    }
}

// ---------------- K2: sa_map = sigmoid(conv7x7([avg,max], w1)) ----------------
// 64x16 output tile, 256 threads, 4 horizontal outputs per thread, float4 smem loads.
__global__ void k2_samap(const float* __restrict__ w1) {
    __shared__ float sA[22][80];
    __shared__ float sM[22][80];
    __shared__ float sw[98];
    const int b  = blockIdx.z;
    const int x0 = blockIdx.x * 64, y0 = blockIdx.y * 16;
    const int t  = threadIdx.x;
    if (t < 98) sw[t] = w1[t];
    const float* A = g_avg + b * MN;
    const float* X = g_mx  + b * MN;
    for (int i = t; i < 22 * 70; i += 256) {
        int sy = i / 70, sx = i % 70;
        int gy = y0 + sy - 3, gx = x0 + sx - 3;
        float a = 0.f, m = 0.f;
        if ((unsigned)gy < 256u && (unsigned)gx < 256u) {
            int g = gy * 256 + gx; a = A[g]; m = X[g];
        }
        sA[sy][sx] = a; sM[sy][sx] = m;
    }
    __syncthreads();
    const int row = t >> 4;          // 0..15
    const int cq  = (t & 15) * 4;    // 0..60
    float acc0 = 0.f, acc1 = 0.f, acc2 = 0.f, acc3 = 0.f;
#pragma unroll
    for (int ky = 0; ky < 7; ky++) {
        const float* ra = &sA[row + ky][cq];
        const float* rm = &sM[row + ky][cq];
        float4 a0 = *(const float4*)ra;
        float4 a1 = *(const float4*)(ra + 4);
        float4 a2 = *(const float4*)(ra + 8);
        float4 m0 = *(const float4*)rm;
        float4 m1 = *(const float4*)(rm + 4);
        float4 m2 = *(const float4*)(rm + 8);
        float av[12] = {a0.x,a0.y,a0.z,a0.w,a1.x,a1.y,a1.z,a1.w,a2.x,a2.y,a2.z,a2.w};
        float mv[12] = {m0.x,m0.y,m0.z,m0.w,m1.x,m1.y,m1.z,m1.w,m2.x,m2.y,m2.z,m2.w};
#pragma unroll
        for (int kx = 0; kx < 7; kx++) {
            float wa = sw[ky*7 + kx], wm = sw[49 + ky*7 + kx];
            acc0 = fmaf(av[kx  ], wa, acc0); acc0 = fmaf(mv[kx  ], wm, acc0);
            acc1 = fmaf(av[kx+1], wa, acc1); acc1 = fmaf(mv[kx+1], wm, acc1);
            acc2 = fmaf(av[kx+2], wa, acc2); acc2 = fmaf(mv[kx+2], wm, acc2);
            acc3 = fmaf(av[kx+3], wa, acc3); acc3 = fmaf(mv[kx+3], wm, acc3);
        }
    }
    float4 o;
    o.x = 1.f / (1.f + expf(-acc0));
    o.y = 1.f / (1.f + expf(-acc1));
    o.z = 1.f / (1.f + expf(-acc2));
    o.w = 1.f / (1.f + expf(-acc3));
    *(float4*)(g_sa + b * MN + (y0 + row) * 256 + x0 + cq) = o;
}

// ---------------- K3: gamma/beta convs + mask + Np + band flags ----------------
__global__ void k3_gb(const float* __restrict__ wg, const float* __restrict__ bg,
                      const float* __restrict__ wb, const float* __restrict__ bb) {
    __shared__ float sS[22][80];
    __shared__ float swg[49], swb[49];
    const int b  = blockIdx.z;
    const int x0 = blockIdx.x * 64, y0 = blockIdx.y * 16;
    const int t  = threadIdx.x;
    if (t < 49) { swg[t] = wg[t]; swb[t] = wb[t]; }
    const float* S = g_sa + b * MN;
    for (int i = t; i < 22 * 70; i += 256) {
        int sy = i / 70, sx = i % 70;
        int gy = y0 + sy - 3, gx = x0 + sx - 3;
        float v = 0.f;
        if ((unsigned)gy < 256u && (unsigned)gx < 256u) v = S[gy * 256 + gx];
        sS[sy][sx] = v;
    }
    __syncthreads();
    const int row = t >> 4;
    const int cq  = (t & 15) * 4;
    float g0 = 0.f, g1 = 0.f, g2 = 0.f, g3 = 0.f;
    float b0 = 0.f, b1 = 0.f, b2 = 0.f, b3 = 0.f;
#pragma unroll
    for (int ky = 0; ky < 7; ky++) {
        const float* rs = &sS[row + ky][cq];
        float4 s0 = *(const float4*)rs;
        float4 s1 = *(const float4*)(rs + 4);
        float4 s2 = *(const float4*)(rs + 8);
        float sv[12] = {s0.x,s0.y,s0.z,s0.w,s1.x,s1.y,s1.z,s1.w,s2.x,s2.y,s2.z,s2.w};
#pragma unroll
        for (int kx = 0; kx < 7; kx++) {
            float wgv = swg[ky*7 + kx], wbv = swb[ky*7 + kx];
            g0 = fmaf(sv[kx  ], wgv, g0); b0 = fmaf(sv[kx  ], wbv, b0);
            g1 = fmaf(sv[kx+1], wgv, g1); b1 = fmaf(sv[kx+1], wbv, b1);
            g2 = fmaf(sv[kx+2], wgv, g2); b2 = fmaf(sv[kx+2], wbv, b2);
            g3 = fmaf(sv[kx+3], wgv, g3); b3 = fmaf(sv[kx+3], wbv, b3);
        }
    }
    const int idx = b * MN + (y0 + row) * 256 + x0 + cq;
    float bgv = bg[0], bbv = bb[0];
    float4 go; go.x = g0 + bgv; go.y = g1 + bgv; go.z = g2 + bgv; go.w = g3 + bgv;
    float4 bo; bo.x = b0 + bbv; bo.y = b1 + bbv; bo.z = b2 + bbv; bo.w = b3 + bbv;
    *(float4*)(g_gam + idx) = go;
    *(float4*)(g_bet + idx) = bo;
    uchar4 mk;
    mk.x = sS[row + 3][cq + 3] >= 0.8f ? 1 : 0;
    mk.y = sS[row + 3][cq + 4] >= 0.8f ? 1 : 0;
    mk.z = sS[row + 3][cq + 5] >= 0.8f ? 1 : 0;
    mk.w = sS[row + 3][cq + 6] >= 0.8f ? 1 : 0;
    *(uchar4*)(g_mask + idx) = mk;
    int cnt = (int)mk.x + mk.y + mk.z + mk.w;
    unsigned tot = __reduce_add_sync(0xffffffffu, (unsigned)cnt);
    unsigned bal = __ballot_sync(0xffffffffu, cnt != 0);
    if ((t & 31) == 0 && tot)  atomicAdd(&g_np, tot);
    if ((t & 31) == 0 && bal)  atomicOr(&g_flag[b * 16 + blockIdx.y], 1u);
}

// ---------------- K4: per-channel MASKED sums over flagged bands only ----------------
__global__ void k4_stats(const float* __restrict__ x) {
    const int band = blockIdx.x, c = blockIdx.y, b = blockIdx.z;
    if (g_flag[b * 16 + band] == 0u) return;
    const float* xp = x + (((size_t)(b * CC + c)) << 16) + band * 4096;
    const unsigned char* mp = g_mask + (b << 16) + band * 4096;
    const int t = threadIdx.x;
    float s1 = 0.f, q1 = 0.f;
#pragma unroll
    for (int i = 0; i < 4; i++) {
        int off = (i * 256 + t) * 4;
        float4 xv = *(const float4*)(xp + off);
        uchar4 mk = *(const uchar4*)(mp + off);
        if (mk.x) { s1 += xv.x; q1 = fmaf(xv.x, xv.x, q1); }
        if (mk.y) { s1 += xv.y; q1 = fmaf(xv.y, xv.y, q1); }
        if (mk.z) { s1 += xv.z; q1 = fmaf(xv.z, xv.z, q1); }
        if (mk.w) { s1 += xv.w; q1 = fmaf(xv.w, xv.w, q1); }
    }
#pragma unroll
    for (int o = 16; o; o >>= 1) {
        s1 += __shfl_down_sync(0xffffffffu, s1, o);
        q1 += __shfl_down_sync(0xffffffffu, q1, o);
    }
    __shared__ float sh[8][2];
    int lane = t & 31, w = t >> 5;
    if (lane == 0) { sh[w][0] = s1; sh[w][1] = q1; }
    __syncthreads();
    if (t < 2) {
        float v = 0.f;
#pragma unroll
        for (int i = 0; i < 8; i++) v += sh[i][t];
        atomicAdd(&g_m[c * 2 + t], (double)v);
    }
}

// ---------------- K5: finalize per-channel params ----------------
__global__ void k5_params() {
    int c = threadIdx.x;
    double s1 = g_m[c*2+0],  q1 = g_m[c*2+1];
    double s2 = g_all[c*2+0] - s1, q2 = g_all[c*2+1] - q1;
    double np = (double)g_np;
    double nq = (double)TOTPIX - np;
    double Sr1 = np > 0.0 ? np : 1.0;
    double Sr2 = nq > 0.0 ? nq : 1.0;
    double mu1 = s1 / Sr1, mu2 = s2 / Sr2;
    double nt  = (double)TOTPIX;
    double v1 = (q1 - s1 * mu1) / nt;
    double v2 = (q2 - s2 * mu2) / nt;
    if (v1 < 0.0) v1 = 0.0;
    if (v2 < 0.0) v2 = 0.0;
    double a1 = sqrt(Sr1 / nt) / sqrt(v1 + 1e-5);
    double a2 = sqrt(Sr2 / nt) / sqrt(v2 + 1e-5);
    g_params[c*4+0] = (float)mu1; g_params[c*4+1] = (float)a1;
    g_params[c*4+2] = (float)mu2; g_params[c*4+3] = (float)a2;
}

// ---------------- K6: fused output ----------------
__global__ void k6_out(const float* __restrict__ x, float* __restrict__ out) {
    __shared__ float4 sp[CC];
    int t = threadIdx.x;
    if (t < CC) sp[t] = ((const float4*)g_params)[t];
    __syncthreads();
    int tid  = blockIdx.x * blockDim.x + t;
    int base = tid * 4;
    int b    = base >> 16;
    int pix  = base & (MN - 1);
    uchar4 mk = *(const uchar4*)(g_mask + base);
    float4 gm = *(const float4*)(g_gam + base);
    float4 bt = *(const float4*)(g_bet + base);
    float g0 = 1.f + gm.x, g1 = 1.f + gm.y, g2 = 1.f + gm.z, g3 = 1.f + gm.w;
    const float* xb = x   + ((size_t)b << 22) + pix;
    float*       ob = out + ((size_t)b << 22) + pix;
#pragma unroll 4
    for (int c = 0; c < CC; c++) {
        float4 xv = *(const float4*)(xb + ((size_t)c << 16));
        float4 p  = sp[c];
        float4 o;
        float mu, a;
        mu = mk.x ? p.x : p.z; a = mk.x ? p.y : p.w; o.x = (xv.x - mu) * (a * g0) + bt.x;
        mu = mk.y ? p.x : p.z; a = mk.y ? p.y : p.w; o.y = (xv.y - mu) * (a * g1) + bt.y;
        mu = mk.z ? p.x : p.z; a = mk.z ? p.y : p.w; o.z = (xv.z - mu) * (a * g2) + bt.z;
        mu = mk.w ? p.x : p.z; a = mk.w ? p.y : p.w; o.w = (xv.w - mu) * (a * g3) + bt.w;
        *(float4*)(ob + ((size_t)c << 16)) = o;
    }
}

extern "C" void kernel_launch(void* const* d_in, const int* in_sizes, int n_in,
                              void* d_out, int out_size) {
    const float* x  = (const float*)d_in[0];
    const float* w1 = (const float*)d_in[1];
    const float* wg = (const float*)d_in[2];
    const float* bg = (const float*)d_in[3];
    const float* wb = (const float*)d_in[4];
    const float* bb = (const float*)d_in[5];
    float* out = (float*)d_out;

    k0_zero<<<1, 256>>>();
    k1_avgmax<<<TOTPIX / 1024, 256>>>(x);
    dim3 cb(256), cg(4, 16, BN);
    k2_samap<<<cg, cb>>>(w1);
    k3_gb<<<cg, cb>>>(wg, bg, wb, bb);
    k4_stats<<<dim3(16, CC, BN), 256>>>(x);
    k5_params<<<1, CC>>>();
    k6_out<<<TOTPIX / 1024, 256>>>(x, out);
}

// round 3
// speedup vs baseline: 1.1094x; 1.1094x over previous
#include <cuda_runtime.h>

#define BN 8
#define CC 64
#define MM 256
#define NNX 256
#define MN (MM*NNX)          // 65536
#define TOTPIX (BN*MN)       // 524288

__device__ float g_avg[TOTPIX];
__device__ float g_mx [TOTPIX];
__device__ float g_gam[TOTPIX];
__device__ float g_bet[TOTPIX];
__device__ unsigned char g_mask[TOTPIX];
__device__ double g_stats[CC*4];      // s1, q1, s2, q2 per channel
__device__ unsigned int g_np;

// ---------------- K0: zero accumulators ----------------
__global__ void k0_zero() {
    int t = threadIdx.x;
    if (t < CC*4) g_stats[t] = 0.0;
    if (t == 0)   g_np = 0u;
}

// ---------------- K1: channel avg + max (8 pixels / thread) ----------------
__global__ void k1_avgmax(const float* __restrict__ x) {
    const int t = threadIdx.x;
    const int blockbase = blockIdx.x * 2048;      // global (b,pix) linear base
    const int b = blockbase >> 16;
    const int pixA = (blockbase & (MN - 1)) + t * 4;
    const float* xb = x + ((size_t)b << 22) + pixA;

    float4 sA, mA, sB, mB;
#pragma unroll 8
    for (int c = 0; c < CC; c++) {
        const float* p = xb + ((size_t)c << 16);
        float4 vA = *(const float4*)(p);
        float4 vB = *(const float4*)(p + 1024);
        if (c == 0) { sA = vA; mA = vA; sB = vB; mB = vB; }
        else {
            sA.x += vA.x; sA.y += vA.y; sA.z += vA.z; sA.w += vA.w;
            mA.x = fmaxf(mA.x, vA.x); mA.y = fmaxf(mA.y, vA.y);
            mA.z = fmaxf(mA.z, vA.z); mA.w = fmaxf(mA.w, vA.w);
            sB.x += vB.x; sB.y += vB.y; sB.z += vB.z; sB.w += vB.w;
            mB.x = fmaxf(mB.x, vB.x); mB.y = fmaxf(mB.y, vB.y);
            mB.z = fmaxf(mB.z, vB.z); mB.w = fmaxf(mB.w, vB.w);
        }
    }
    const float inv = 1.0f / 64.0f;
    float4 aA; aA.x = sA.x*inv; aA.y = sA.y*inv; aA.z = sA.z*inv; aA.w = sA.w*inv;
    float4 aB; aB.x = sB.x*inv; aB.y = sB.y*inv; aB.z = sB.z*inv; aB.w = sB.w*inv;
    const int base = blockbase + t * 4;
    *(float4*)(g_avg + base)        = aA;
    *(float4*)(g_mx  + base)        = mA;
    *(float4*)(g_avg + base + 1024) = aB;
    *(float4*)(g_mx  + base + 1024) = mB;
}

// ---------------- K23: sa conv (recomputed w/ halo) + gamma/beta conv + mask + Np ----------------
// Output tile 64x16. sa needed on 22x70 (halo 3); avg/max on 28x78 (halo 6).
__global__ void k23_conv(const float* __restrict__ w1,
                         const float* __restrict__ wg, const float* __restrict__ bg,
                         const float* __restrict__ wb, const float* __restrict__ bb) {
    __shared__ float sAvg[28][80];
    __shared__ float sMax[28][80];
    __shared__ float sSa [22][76];
    __shared__ float sw1[98], swg[49], swb[49];
    const int b  = blockIdx.z;
    const int x0 = blockIdx.x * 64, y0 = blockIdx.y * 16;
    const int t  = threadIdx.x;
    if (t < 98) sw1[t] = w1[t];
    if (t < 49) { swg[t] = wg[t]; swb[t] = wb[t]; }

    // Phase 0: load avg/max tile+halo6 (28 rows x 80 cols, cols -6..73 rel x0)
    const float* A = g_avg + b * MN;
    const float* X = g_mx  + b * MN;
    for (int i = t; i < 28 * 80; i += 256) {
        int sy = i / 80, sx = i % 80;
        int gy = y0 + sy - 6, gx = x0 + sx - 6;
        float a = 0.f, m = 0.f;
        if ((unsigned)gy < 256u && (unsigned)gx < 256u) {
            int g = gy * 256 + gx; a = A[g]; m = X[g];
        }
        sAvg[sy][sx] = a; sMax[sy][sx] = m;
    }
    __syncthreads();

    // Phase 1: compute sa on 22 rows x 72 cols (18 quad groups), rel coords:
    // sSa[sy][sx] = sa(y0-3+sy, x0-3+sx); avg index = [sy+ky][sxq+j+kx]
    for (int task = t; task < 22 * 18; task += 256) {
        const int sy  = task / 18;
        const int sxq = (task % 18) * 4;
        float acc0 = 0.f, acc1 = 0.f, acc2 = 0.f, acc3 = 0.f;
#pragma unroll
        for (int ky = 0; ky < 7; ky++) {
            const float* ra = &sAvg[sy + ky][sxq];
            const float* rm = &sMax[sy + ky][sxq];
            float4 a0 = *(const float4*)ra;
            float4 a1 = *(const float4*)(ra + 4);
            float4 a2 = *(const float4*)(ra + 8);
            float4 m0 = *(const float4*)rm;
            float4 m1 = *(const float4*)(rm + 4);
            float4 m2 = *(const float4*)(rm + 8);
            float av[12] = {a0.x,a0.y,a0.z,a0.w,a1.x,a1.y,a1.z,a1.w,a2.x,a2.y,a2.z,a2.w};
            float mv[12] = {m0.x,m0.y,m0.z,m0.w,m1.x,m1.y,m1.z,m1.w,m2.x,m2.y,m2.z,m2.w};
#pragma unroll
            for (int kx = 0; kx < 7; kx++) {
                float wa = sw1[ky*7 + kx], wm = sw1[49 + ky*7 + kx];
                acc0 = fmaf(av[kx  ], wa, acc0); acc0 = fmaf(mv[kx  ], wm, acc0);
                acc1 = fmaf(av[kx+1], wa, acc1); acc1 = fmaf(mv[kx+1], wm, acc1);
                acc2 = fmaf(av[kx+2], wa, acc2); acc2 = fmaf(mv[kx+2], wm, acc2);
                acc3 = fmaf(av[kx+3], wa, acc3); acc3 = fmaf(mv[kx+3], wm, acc3);
            }
        }
        const int ys = y0 - 3 + sy;
        const int xs = x0 - 3 + sxq;
        bool rowok = (unsigned)ys < 256u;
        sSa[sy][sxq  ] = (rowok && (unsigned)(xs  ) < 256u) ? 1.f/(1.f+expf(-acc0)) : 0.f;
        sSa[sy][sxq+1] = (rowok && (unsigned)(xs+1) < 256u) ? 1.f/(1.f+expf(-acc1)) : 0.f;
        sSa[sy][sxq+2] = (rowok && (unsigned)(xs+2) < 256u) ? 1.f/(1.f+expf(-acc2)) : 0.f;
        sSa[sy][sxq+3] = (rowok && (unsigned)(xs+3) < 256u) ? 1.f/(1.f+expf(-acc3)) : 0.f;
    }
    __syncthreads();

    // Phase 2: gamma/beta conv + mask for out tile; out (y0+row, x0+cq..cq+3)
    const int row = t >> 4;
    const int cq  = (t & 15) * 4;
    float g0 = 0.f, g1 = 0.f, g2 = 0.f, g3 = 0.f;
    float b0 = 0.f, b1 = 0.f, b2 = 0.f, b3 = 0.f;
#pragma unroll
    for (int ky = 0; ky < 7; ky++) {
        const float* rs = &sSa[row + ky][cq];
        float4 s0 = *(const float4*)rs;
        float4 s1 = *(const float4*)(rs + 4);
        float4 s2 = *(const float4*)(rs + 8);
        float sv[12] = {s0.x,s0.y,s0.z,s0.w,s1.x,s1.y,s1.z,s1.w,s2.x,s2.y,s2.z,s2.w};
#pragma unroll
        for (int kx = 0; kx < 7; kx++) {
            float wgv = swg[ky*7 + kx], wbv = swb[ky*7 + kx];
            g0 = fmaf(sv[kx  ], wgv, g0); b0 = fmaf(sv[kx  ], wbv, b0);
            g1 = fmaf(sv[kx+1], wgv, g1); b1 = fmaf(sv[kx+1], wbv, b1);
            g2 = fmaf(sv[kx+2], wgv, g2); b2 = fmaf(sv[kx+2], wbv, b2);
            g3 = fmaf(sv[kx+3], wgv, g3); b3 = fmaf(sv[kx+3], wbv, b3);
        }
    }
    const int idx = b * MN + (y0 + row) * 256 + x0 + cq;
    const float bgv = bg[0], bbv = bb[0];
    float4 go; go.x = g0 + bgv; go.y = g1 + bgv; go.z = g2 + bgv; go.w = g3 + bgv;
    float4 bo; bo.x = b0 + bbv; bo.y = b1 + bbv; bo.z = b2 + bbv; bo.w = b3 + bbv;
    *(float4*)(g_gam + idx) = go;
    *(float4*)(g_bet + idx) = bo;
    uchar4 mk;
    mk.x = sSa[row + 3][cq + 3] >= 0.8f ? 1 : 0;
    mk.y = sSa[row + 3][cq + 4] >= 0.8f ? 1 : 0;
    mk.z = sSa[row + 3][cq + 5] >= 0.8f ? 1 : 0;
    mk.w = sSa[row + 3][cq + 6] >= 0.8f ? 1 : 0;
    *(uchar4*)(g_mask + idx) = mk;
    int cnt = (int)mk.x + mk.y + mk.z + mk.w;
    unsigned tot = __reduce_add_sync(0xffffffffu, (unsigned)cnt);
    if ((t & 31) == 0 && tot) atomicAdd(&g_np, tot);
}

// ---------------- K4: per-channel masked sums (full read, branchless) ----------------
__global__ void k4_stats(const float* __restrict__ x) {
    const int b = blockIdx.z, c = blockIdx.y, chunk = blockIdx.x;  // 4 chunks/plane
    const float* xp = x + (((size_t)(b * CC + c)) << 16);
    const unsigned char* mp = g_mask + (b << 16);
    const int t = threadIdx.x;
    float s1 = 0.f, q1 = 0.f, s2 = 0.f, q2 = 0.f;
#pragma unroll 4
    for (int i = 0; i < 16; i++) {
        int pix = (chunk * 4096 + i * 256 + t) * 4;
        float4 xv = *(const float4*)(xp + pix);
        uchar4 mk = *(const uchar4*)(mp + pix);
        float m, n;
        m = mk.x ? 1.f : 0.f; n = 1.f - m;
        s1 = fmaf(m, xv.x, s1); q1 = fmaf(m * xv.x, xv.x, q1);
        s2 = fmaf(n, xv.x, s2); q2 = fmaf(n * xv.x, xv.x, q2);
        m = mk.y ? 1.f : 0.f; n = 1.f - m;
        s1 = fmaf(m, xv.y, s1); q1 = fmaf(m * xv.y, xv.y, q1);
        s2 = fmaf(n, xv.y, s2); q2 = fmaf(n * xv.y, xv.y, q2);
        m = mk.z ? 1.f : 0.f; n = 1.f - m;
        s1 = fmaf(m, xv.z, s1); q1 = fmaf(m * xv.z, xv.z, q1);
        s2 = fmaf(n, xv.z, s2); q2 = fmaf(n * xv.z, xv.z, q2);
        m = mk.w ? 1.f : 0.f; n = 1.f - m;
        s1 = fmaf(m, xv.w, s1); q1 = fmaf(m * xv.w, xv.w, q1);
        s2 = fmaf(n, xv.w, s2); q2 = fmaf(n * xv.w, xv.w, q2);
    }
#pragma unroll
    for (int o = 16; o; o >>= 1) {
        s1 += __shfl_down_sync(0xffffffffu, s1, o);
        q1 += __shfl_down_sync(0xffffffffu, q1, o);
        s2 += __shfl_down_sync(0xffffffffu, s2, o);
        q2 += __shfl_down_sync(0xffffffffu, q2, o);
    }
    __shared__ float sh[8][4];
    int lane = t & 31, w = t >> 5;
    if (lane == 0) { sh[w][0] = s1; sh[w][1] = q1; sh[w][2] = s2; sh[w][3] = q2; }
    __syncthreads();
    if (t < 4) {
        float v = 0.f;
#pragma unroll
        for (int i = 0; i < 8; i++) v += sh[i][t];
        atomicAdd(&g_stats[c * 4 + t], (double)v);
    }
}

// ---------------- K6: params (inlined) + fused output ----------------
__global__ void k6_out(const float* __restrict__ x, float* __restrict__ out) {
    __shared__ float4 sp[CC];
    const int t = threadIdx.x;
    if (t < CC) {
        double s1 = g_stats[t*4+0], q1 = g_stats[t*4+1];
        double s2 = g_stats[t*4+2], q2 = g_stats[t*4+3];
        double np = (double)g_np;
        double nq = (double)TOTPIX - np;
        double Sr1 = np > 0.0 ? np : 1.0;
        double Sr2 = nq > 0.0 ? nq : 1.0;
        double mu1 = s1 / Sr1, mu2 = s2 / Sr2;
        double nt  = (double)TOTPIX;
        double v1 = (q1 - s1 * mu1) / nt;
        double v2 = (q2 - s2 * mu2) / nt;
        if (v1 < 0.0) v1 = 0.0;
        if (v2 < 0.0) v2 = 0.0;
        double a1 = sqrt(Sr1 / nt) / sqrt(v1 + 1e-5);
        double a2 = sqrt(Sr2 / nt) / sqrt(v2 + 1e-5);
        float4 p; p.x = (float)mu1; p.y = (float)a1; p.z = (float)mu2; p.w = (float)a2;
        sp[t] = p;
    }
    __syncthreads();
    const int tid  = blockIdx.x * blockDim.x + t;
    const int base = tid * 4;
    const int b    = base >> 16;
    const int pix  = base & (MN - 1);
    uchar4 mk = *(const uchar4*)(g_mask + base);
    float4 gm = *(const float4*)(g_gam + base);
    float4 bt = *(const float4*)(g_bet + base);
    float g0 = 1.f + gm.x, g1 = 1.f + gm.y, g2 = 1.f + gm.z, g3 = 1.f + gm.w;
    const float* xb = x   + ((size_t)b << 22) + pix;
    float*       ob = out + ((size_t)b << 22) + pix;
#pragma unroll 4
    for (int c = 0; c < CC; c++) {
        float4 xv = *(const float4*)(xb + ((size_t)c << 16));
        float4 p  = sp[c];
        float4 o;
        float mu, a;
        mu = mk.x ? p.x : p.z; a = mk.x ? p.y : p.w; o.x = (xv.x - mu) * (a * g0) + bt.x;
        mu = mk.y ? p.x : p.z; a = mk.y ? p.y : p.w; o.y = (xv.y - mu) * (a * g1) + bt.y;
        mu = mk.z ? p.x : p.z; a = mk.z ? p.y : p.w; o.z = (xv.z - mu) * (a * g2) + bt.z;
        mu = mk.w ? p.x : p.z; a = mk.w ? p.y : p.w; o.w = (xv.w - mu) * (a * g3) + bt.w;
        *(float4*)(ob + ((size_t)c << 16)) = o;
    }
}

extern "C" void kernel_launch(void* const* d_in, const int* in_sizes, int n_in,
                              void* d_out, int out_size) {
    const float* x  = (const float*)d_in[0];
    const float* w1 = (const float*)d_in[1];
    const float* wg = (const float*)d_in[2];
    const float* bg = (const float*)d_in[3];
    const float* wb = (const float*)d_in[4];
    const float* bb = (const float*)d_in[5];
    float* out = (float*)d_out;

    k0_zero<<<1, 256>>>();
    k1_avgmax<<<TOTPIX / 2048, 256>>>(x);
    k23_conv<<<dim3(4, 16, BN), 256>>>(w1, wg, bg, wb, bb);
    k4_stats<<<dim3(4, CC, BN), 256>>>(x);
    k6_out<<<TOTPIX / 1024, 256>>>(x, out);
}